// round 6
// baseline (speedup 1.0000x reference)
#include <cuda_runtime.h>
#include <cuda_bf16.h>
#include <math.h>

// Problem constants
#define NUM_PLANES 1344          // 64 batches * 21 joints
#define IMG        256
#define PLANE_F8   (IMG * IMG / 8)   // 8192 32-byte chunks per plane
#define SEGS       8                 // segments per plane (grid.y)
#define SEG_F8     (PLANE_F8 / SEGS) // 1024 chunks per block (32 rows)
#define SEG_ROWS   (IMG / SEGS)      // 32 rows per segment
#define ITERS      (SEG_F8 / 256)    // 4 iterations of 256 threads

// g1[a+5] = exp(-a^2 / (2 * 2.5^2)), a in [-5,5]. Peak-to-one separable gaussian:
// reference kernel value k[i][j] == g1[i]*g1[j] to within ~1 ulp.
__constant__ float c_g1[11] = {
    0.13533528323661270f,  // exp(-2.00)
    0.27803730045319414f,  // exp(-1.28)
    0.48675225595997157f,  // exp(-0.72)
    0.72614903707369012f,  // exp(-0.32)
    0.92311634638663580f,  // exp(-0.08)
    1.0f,
    0.92311634638663580f,
    0.72614903707369012f,
    0.48675225595997157f,
    0.27803730045319414f,
    0.13533528323661270f
};

// Blackwell 256-bit store: one STG.E.256 (half the L1 tag ops / LSU issues of 2x STG.128)
__device__ __forceinline__ void stg256(float* p, const float v[8])
{
    asm volatile(
        "st.global.v8.b32 [%0], {%1, %2, %3, %4, %5, %6, %7, %8};"
        :: "l"(p),
           "r"(__float_as_uint(v[0])), "r"(__float_as_uint(v[1])),
           "r"(__float_as_uint(v[2])), "r"(__float_as_uint(v[3])),
           "r"(__float_as_uint(v[4])), "r"(__float_as_uint(v[5])),
           "r"(__float_as_uint(v[6])), "r"(__float_as_uint(v[7]))
        : "memory");
}

__global__ void __launch_bounds__(256)
fisheye_heatmap_kernel(const float* __restrict__ joint, float* __restrict__ out)
{
    const int plane = blockIdx.x;   // 0..1343  (b*21 + j)
    const int seg   = blockIdx.y;   // 0..SEGS-1

    // ---- fisheye projection for this plane (redundant per thread; trivial cost) ----
    const float x = joint[plane * 3 + 0];
    const float y = joint[plane * 3 + 1];
    const float z = joint[plane * 3 + 2];

    const float rxy   = sqrtf(x * x + y * y);
    const float theta = atan2f(rxy, z);
    const float phi   = atan2f(y, x);
    // r = RADIUS * theta / (pi/2); keep the division to match reference rounding
    const float r = (128.0f * theta) / 1.5707963267948966f;

    float sphi, cphi;
    sincosf(phi, &sphi, &cphi);

    // jnp.round == round-half-to-even == rintf in default RN mode
    const float fx = rintf(128.0f + r * cphi);
    const float fy = rintf(128.0f + r * sphi);

    int ix = (int)fx; ix = min(255, max(0, ix));
    int iy = (int)fy; iy = min(255, max(0, iy));

    // ---- this block's 32-row segment ----
    float* __restrict__ po = out + (size_t)plane * IMG * IMG + seg * SEG_F8 * 8;
    const int row0 = seg * SEG_ROWS;

    const float zero8[8] = {0.f, 0.f, 0.f, 0.f, 0.f, 0.f, 0.f, 0.f};

    // Fast path: segment cannot intersect the 11-row gaussian band -> pure zero fill.
    const bool touches = (iy + 5 >= row0) && (iy - 5 <= row0 + SEG_ROWS - 1);
    if (!touches) {
        #pragma unroll
        for (int it = 0; it < ITERS; ++it)
            stg256(po + (threadIdx.x + it * 256) * 8, zero8);
        return;
    }

    // Slow path (at most 2 of 8 segments per plane).
    // Layout: 32 chunks of 8 floats per row -> one warp-iteration == one image row,
    // so the gaussian-row branch is exactly warp-uniform.
    const int iy5 = iy - 5;   // dy = row - iy5 in [0,10]
    const int ix5 = ix - 5;

    #pragma unroll
    for (int it = 0; it < ITERS; ++it) {
        const int i   = threadIdx.x + it * 256;   // chunk index within segment
        const int row = row0 + (i >> 5);          // 32 chunks per row
        const int dy  = row - iy5;

        if ((unsigned)dy < 11u) {                 // warp-uniform
            const float gy  = c_g1[dy];
            const int   dx0 = ((i & 31) << 3) - ix5;
            float v[8];
            #pragma unroll
            for (int e = 0; e < 8; ++e)
                v[e] = ((unsigned)(dx0 + e) < 11u) ? gy * c_g1[dx0 + e] : 0.f;
            stg256(po + i * 8, v);
        } else {
            stg256(po + i * 8, zero8);
        }
    }
}

extern "C" void kernel_launch(void* const* d_in, const int* in_sizes, int n_in,
                              void* d_out, int out_size)
{
    const float* joint = (const float*)d_in[0];   // [64, 21, 3] f32
    float* out = (float*)d_out;                   // [64, 21, 256, 256] f32

    dim3 grid(NUM_PLANES, SEGS);
    fisheye_heatmap_kernel<<<grid, 256>>>(joint, out);
}